// round 1
// baseline (speedup 1.0000x reference)
#include <cuda_runtime.h>
#include <cuda_bf16.h>
#include <float.h>

#define N_ROWS   131072
#define DIM      128
#define K_CODES  4096
#define DECAY    0.99f
#define ONE_M_D  0.01f
#define EPS      1e-5f

// Output layout (tuple order, flattened, f32):
// quantize_st [N,DIM], quant_loss [1], n_small [1], embed_ind [N],
// embed_new [DIM,K], cluster_size_new [K], embed_avg_new [DIM,K]
#define OFF_Q      0
#define OFF_LOSS   16777216
#define OFF_NSMALL 16777217
#define OFF_IND    16777218
#define OFF_ENEW   16908290
#define OFF_CS     17432578
#define OFF_EAVG   17436674

// Scratch (static device globals -- no allocation)
__device__ __align__(16) float  g_embedT[K_CODES * DIM];  // codeword-major
__device__ __align__(16) float  g_enorm[K_CODES];
__device__ double g_loss;
__device__ float  g_n;

// ---------------------------------------------------------------------------
// K0: transpose embed, pre-scale EMA state into output regions, zero loss
// ---------------------------------------------------------------------------
__global__ void k_init(const float* __restrict__ embed,
                       const float* __restrict__ cluster_size,
                       const float* __restrict__ embed_avg,
                       float* __restrict__ out) {
    int i = blockIdx.x * 256 + threadIdx.x;
    if (i < DIM * K_CODES) {
        out[OFF_EAVG + i] = embed_avg[i] * DECAY;
        int d = i >> 12;          // i / 4096
        int k = i & (K_CODES - 1);
        g_embedT[k * DIM + d] = embed[i];
    }
    if (i < K_CODES) out[OFF_CS + i] = cluster_size[i] * DECAY;
    if (i == 0) g_loss = 0.0;
}

// ---------------------------------------------------------------------------
// K0b: per-codeword squared norm (warp per code, from coalesced embedT)
// ---------------------------------------------------------------------------
__global__ void k_enorm() {
    int gid  = blockIdx.x * 256 + threadIdx.x;
    int k    = gid >> 5;
    int lane = gid & 31;
    float4 v = ((const float4*)(g_embedT + k * DIM))[lane];
    float s = v.x * v.x + v.y * v.y + v.z * v.z + v.w * v.w;
    #pragma unroll
    for (int o = 16; o > 0; o >>= 1) s += __shfl_down_sync(0xffffffffu, s, o);
    if (lane == 0) g_enorm[k] = s;
}

// ---------------------------------------------------------------------------
// K1: main GEMM + argmin + epilogue (quantize, loss, EMA scatter)
// 64 rows/block, 256 threads, 4x4 microtile, 64-col codebook chunks
// ---------------------------------------------------------------------------
__global__ void __launch_bounds__(256, 2)
k_main(const float* __restrict__ x,
       const float* __restrict__ embed,
       float* __restrict__ out) {
    extern __shared__ float smem[];
    float* xs = smem;              // [128][64] x transposed: xs[d*64 + r]
    float* es = smem + 8192;       // [128][64] embed chunk:  es[d*64 + c]
    float* en = smem + 16384;      // [64] chunk of enorm
    int*   rowidx = (int*)(smem + 16448); // [64]

    const int t  = threadIdx.x;
    const int tx = t & 15;
    const int ty = t >> 4;
    const int row0 = blockIdx.x * 64;

    // Load x tile transposed: xs[d][r]
    for (int i = t; i < 2048; i += 256) {
        int r  = i >> 5;          // 32 float4 per row of 128
        int d4 = (i & 31) * 4;
        float4 v = *(const float4*)(x + (size_t)(row0 + r) * DIM + d4);
        xs[(d4 + 0) * 64 + r] = v.x;
        xs[(d4 + 1) * 64 + r] = v.y;
        xs[(d4 + 2) * 64 + r] = v.z;
        xs[(d4 + 3) * 64 + r] = v.w;
    }
    __syncthreads();

    float bestv[4];
    int   besti[4];
    #pragma unroll
    for (int i = 0; i < 4; i++) { bestv[i] = FLT_MAX; besti[i] = 0; }

    for (int c0 = 0; c0 < K_CODES; c0 += 64) {
        // load embed chunk [128 dims][64 cols]
        for (int i = t; i < 2048; i += 256) {
            int d  = i >> 4;
            int cc = (i & 15) * 4;
            float4 v = *(const float4*)(embed + (size_t)d * K_CODES + c0 + cc);
            *(float4*)(es + d * 64 + cc) = v;
        }
        if (t < 16) ((float4*)en)[t] = ((const float4*)(g_enorm + c0))[t];
        __syncthreads();

        float acc[4][4];
        #pragma unroll
        for (int i = 0; i < 4; i++)
            #pragma unroll
            for (int j = 0; j < 4; j++) acc[i][j] = 0.f;

        #pragma unroll 8
        for (int d = 0; d < DIM; d++) {
            float4 a = *(const float4*)(xs + d * 64 + ty * 4);
            float4 b = *(const float4*)(es + d * 64 + tx * 4);
            acc[0][0] += a.x * b.x; acc[0][1] += a.x * b.y;
            acc[0][2] += a.x * b.z; acc[0][3] += a.x * b.w;
            acc[1][0] += a.y * b.x; acc[1][1] += a.y * b.y;
            acc[1][2] += a.y * b.z; acc[1][3] += a.y * b.w;
            acc[2][0] += a.z * b.x; acc[2][1] += a.z * b.y;
            acc[2][2] += a.z * b.z; acc[2][3] += a.z * b.w;
            acc[3][0] += a.w * b.x; acc[3][1] += a.w * b.y;
            acc[3][2] += a.w * b.z; acc[3][3] += a.w * b.w;
        }

        #pragma unroll
        for (int j = 0; j < 4; j++) {
            float e   = en[tx * 4 + j];
            int   col = c0 + tx * 4 + j;
            #pragma unroll
            for (int i = 0; i < 4; i++) {
                float s = e - 2.0f * acc[i][j];
                if (s < bestv[i] || (s == bestv[i] && col < besti[i])) {
                    bestv[i] = s; besti[i] = col;
                }
            }
        }
        __syncthreads();
    }

    // cross-thread argmin reduce (reuse es region)
    float* redv = es;                 // [64][16]
    int*   redi = (int*)(es + 1024);  // [64][16]
    #pragma unroll
    for (int i = 0; i < 4; i++) {
        redv[(ty * 4 + i) * 16 + tx] = bestv[i];
        redi[(ty * 4 + i) * 16 + tx] = besti[i];
    }
    __syncthreads();

    if (t < 64) {
        float bv = FLT_MAX; int bi = 0x7fffffff;
        #pragma unroll
        for (int j = 0; j < 16; j++) {
            float v = redv[t * 16 + j];
            int   idx = redi[t * 16 + j];
            if (v < bv || (v == bv && idx < bi)) { bv = v; bi = idx; }
        }
        rowidx[t] = bi;
        out[OFF_IND + row0 + t] = (float)bi;
        atomicAdd(out + OFF_CS + bi, ONE_M_D);
    }
    __syncthreads();

    // per-row epilogue: quantize copy, loss, EMA scatter
    const int warp = t >> 5, lane = t & 31;
    float lsum = 0.f;
    for (int r8 = 0; r8 < 8; r8++) {
        int row  = warp * 8 + r8;
        int grow = row0 + row;
        int idx  = rowidx[row];
        float4 q  = *(const float4*)(g_embedT + (size_t)idx * DIM + lane * 4);
        float4 xv = *(const float4*)(x + (size_t)grow * DIM + lane * 4);
        *(float4*)(out + OFF_Q + (size_t)grow * DIM + lane * 4) = q;
        float d0 = q.x - xv.x, d1 = q.y - xv.y, d2 = q.z - xv.z, d3 = q.w - xv.w;
        lsum += d0 * d0 + d1 * d1 + d2 * d2 + d3 * d3;
        atomicAdd(out + OFF_EAVG + (size_t)(lane * 4 + 0) * K_CODES + idx, ONE_M_D * xv.x);
        atomicAdd(out + OFF_EAVG + (size_t)(lane * 4 + 1) * K_CODES + idx, ONE_M_D * xv.y);
        atomicAdd(out + OFF_EAVG + (size_t)(lane * 4 + 2) * K_CODES + idx, ONE_M_D * xv.z);
        atomicAdd(out + OFF_EAVG + (size_t)(lane * 4 + 3) * K_CODES + idx, ONE_M_D * xv.w);
    }
    #pragma unroll
    for (int o = 16; o > 0; o >>= 1) lsum += __shfl_down_sync(0xffffffffu, lsum, o);
    if (lane == 0) atomicAdd(&g_loss, (double)lsum);
}

// ---------------------------------------------------------------------------
// K2: n = sum(cluster_size_new), n_small = count(< 1)
// ---------------------------------------------------------------------------
__global__ void k_scalar(float* __restrict__ out) {
    __shared__ float ssum[32];
    __shared__ int   scnt[32];
    int t = threadIdx.x;
    float s = 0.f; int c = 0;
    #pragma unroll
    for (int j = 0; j < 4; j++) {
        float v = out[OFF_CS + t + j * 1024];
        s += v;
        c += (v < 1.0f) ? 1 : 0;
    }
    #pragma unroll
    for (int o = 16; o > 0; o >>= 1) {
        s += __shfl_down_sync(0xffffffffu, s, o);
        c += __shfl_down_sync(0xffffffffu, c, o);
    }
    if ((t & 31) == 0) { ssum[t >> 5] = s; scnt[t >> 5] = c; }
    __syncthreads();
    if (t < 32) {
        s = ssum[t]; c = scnt[t];
        #pragma unroll
        for (int o = 16; o > 0; o >>= 1) {
            s += __shfl_down_sync(0xffffffffu, s, o);
            c += __shfl_down_sync(0xffffffffu, c, o);
        }
        if (t == 0) { g_n = s; out[OFF_NSMALL] = (float)c; }
    }
}

// ---------------------------------------------------------------------------
// K3: embed_new = embed_avg_new / cs_norm ; finalize loss
// ---------------------------------------------------------------------------
__global__ void k_final(float* __restrict__ out) {
    int i = blockIdx.x * 256 + threadIdx.x;
    if (i < DIM * K_CODES) {
        int k = i & (K_CODES - 1);
        float n  = g_n;
        float cs = out[OFF_CS + k];
        float csn = (cs + EPS) / (n + (float)K_CODES * EPS) * n;
        out[OFF_ENEW + i] = out[OFF_EAVG + i] / csn;
    }
    if (i == 0) out[OFF_LOSS] = (float)(g_loss / ((double)N_ROWS * (double)DIM));
}

// ---------------------------------------------------------------------------
extern "C" void kernel_launch(void* const* d_in, const int* in_sizes, int n_in,
                              void* d_out, int out_size) {
    const float* x            = (const float*)d_in[0];
    const float* embed        = (const float*)d_in[1];
    const float* cluster_size = (const float*)d_in[2];
    const float* embed_avg    = (const float*)d_in[3];
    float* out = (float*)d_out;

    const int smem_main = (16448 + 64) * (int)sizeof(float); // 66048 B
    cudaFuncSetAttribute(k_main, cudaFuncAttributeMaxDynamicSharedMemorySize, smem_main);

    k_init<<<(DIM * K_CODES + 255) / 256, 256>>>(embed, cluster_size, embed_avg, out);
    k_enorm<<<(K_CODES * 32) / 256, 256>>>();
    k_main<<<N_ROWS / 64, 256, smem_main>>>(x, embed, out);
    k_scalar<<<1, 1024>>>(out);
    k_final<<<(DIM * K_CODES + 255) / 256, 256>>>(out);
}

// round 3
// speedup vs baseline: 1.5771x; 1.5771x over previous
#include <cuda_runtime.h>
#include <cuda_fp16.h>
#include <float.h>
#include <stdint.h>

#define N_ROWS   131072
#define DIM      128
#define K_CODES  4096
#define DECAY    0.99f
#define ONE_M_D  0.01f
#define EPS      1e-5f
#define MARGIN   2e-3f

// Output layout (tuple order, flattened, f32)
#define OFF_Q      0
#define OFF_LOSS   16777216
#define OFF_NSMALL 16777217
#define OFF_IND    16777218
#define OFF_ENEW   16908290
#define OFF_CS     17432578
#define OFF_EAVG   17436674

// ---------------- device scratch (no allocation) ----------------
__device__ __align__(16) float  g_embedT[K_CODES * DIM];  // codeword-major fp32
__device__ __align__(16) __half g_ehi[K_CODES * DIM];     // codeword-major fp16 hi
__device__ __align__(16) __half g_elo[K_CODES * DIM];     // codeword-major fp16 lo
__device__ __align__(16) float  g_enorm[K_CODES];
__device__ double g_loss;
__device__ float  g_n;
__device__ int    g_fixn;
__device__ int    g_fixlist[4096];
__device__ int    g_hist[K_CODES];
__device__ int    g_off[K_CODES];
__device__ int    g_cur[K_CODES];
__device__ int    g_rowlist[N_ROWS];

// ---------------- helpers ----------------
#define CP_ASYNC16(dst, src) \
    asm volatile("cp.async.cg.shared.global [%0], [%1], 16;" :: "r"(dst), "l"(src) : "memory")
#define CP_COMMIT() asm volatile("cp.async.commit_group;" ::: "memory")
#define CP_WAIT(n)  asm volatile("cp.async.wait_group %0;" :: "n"(n) : "memory")

__device__ __forceinline__ uint32_t s2u(const void* p) {
    uint32_t a;
    asm("{ .reg .u64 t; cvta.to.shared.u64 t, %1; cvt.u32.u64 %0, t; }" : "=r"(a) : "l"(p));
    return a;
}

__device__ __forceinline__ void mma16816(float* c, uint32_t a0, uint32_t a1, uint32_t a2,
                                         uint32_t a3, uint32_t b0, uint32_t b1) {
    asm volatile("mma.sync.aligned.m16n8k16.row.col.f32.f16.f16.f32 "
                 "{%0,%1,%2,%3}, {%4,%5,%6,%7}, {%8,%9}, {%0,%1,%2,%3};"
                 : "+f"(c[0]), "+f"(c[1]), "+f"(c[2]), "+f"(c[3])
                 : "r"(a0), "r"(a1), "r"(a2), "r"(a3), "r"(b0), "r"(b1));
}

__device__ __forceinline__ void upd2(float& v1, int& i1, float& v2, float d, int c) {
    if (d < v1)      { v2 = v1; v1 = d; i1 = c; }
    else if (d < v2) { v2 = d; }
}

// smem layout (bytes) for k_mma
#define SM_EN   0
#define SM_AH   16384
#define SM_AL   51200
#define SM_B    86016
#define BUFSZ   34816         // per double-buffer slot (hi 17408 + lo 17408)
#define SMEM_MMA_BYTES 155648
#define RSTRIDE 272           // 136 halves: padded row stride (conflict-free)

// ---------------------------------------------------------------------------
// K0: prescale EMA state into output regions, zero accumulators
// ---------------------------------------------------------------------------
__global__ void k_init(const float* __restrict__ cluster_size,
                       const float* __restrict__ embed_avg,
                       float* __restrict__ out) {
    int i = blockIdx.x * 256 + threadIdx.x;
    if (i < DIM * K_CODES) out[OFF_EAVG + i] = embed_avg[i] * DECAY;
    if (i < K_CODES) {
        out[OFF_CS + i] = cluster_size[i] * DECAY;
        g_hist[i] = 0;
        g_cur[i]  = 0;
    }
    if (i == 0) { g_loss = 0.0; g_fixn = 0; }
}

// ---------------------------------------------------------------------------
// K0b: transpose embed -> embedT fp32 / fp16 hi / fp16 lo (codeword-major)
// ---------------------------------------------------------------------------
__global__ void k_prepe(const float* __restrict__ embed) {
    int i = blockIdx.x * 256 + threadIdx.x;
    if (i >= DIM * K_CODES) return;
    float v = embed[i];
    int d = i >> 12;
    int k = i & (K_CODES - 1);
    int j = k * DIM + d;
    g_embedT[j] = v;
    __half h = __float2half_rn(v);
    g_ehi[j] = h;
    g_elo[j] = __float2half_rn(v - __half2float(h));
}

// ---------------------------------------------------------------------------
// K0c: per-codeword squared norm (exact fp32)
// ---------------------------------------------------------------------------
__global__ void k_enorm() {
    int gid  = blockIdx.x * 256 + threadIdx.x;
    int k    = gid >> 5;
    int lane = gid & 31;
    float4 v = ((const float4*)(g_embedT + k * DIM))[lane];
    float s = v.x * v.x + v.y * v.y + v.z * v.z + v.w * v.w;
    #pragma unroll
    for (int o = 16; o > 0; o >>= 1) s += __shfl_down_sync(0xffffffffu, s, o);
    if (lane == 0) g_enorm[k] = s;
}

// ---------------------------------------------------------------------------
// K1: split-fp16 mma.sync GEMM + per-row top-2 argmin
// block: 128 rows x all 4096 codes (chunks of 64); 256 thr = 8 warps x 16 rows
// ---------------------------------------------------------------------------
__global__ void __launch_bounds__(256, 1)
k_mma(const float* __restrict__ x, float* __restrict__ out) {
    extern __shared__ __align__(16) char smem[];
    const uint32_t sb = s2u(smem);
    const int tid  = threadIdx.x;
    const int warp = tid >> 5;
    const int lane = tid & 31;
    const int g    = lane >> 2;    // 0..7
    const int t4   = lane & 3;     // 0..3
    const int row0 = blockIdx.x * 128;

    // stage enorm (16KB)
    for (int u = tid; u < 1024; u += 256)
        ((float4*)(smem + SM_EN))[u] = ((const float4*)g_enorm)[u];

    // convert x tile (128 rows x 128 dims) to split fp16 in smem (padded stride)
    const float* xb = x + (size_t)row0 * DIM;
    for (int u = tid; u < 4096; u += 256) {
        int r = u >> 5, s = u & 31;           // 32 float4 per row
        float4 v = ((const float4*)(xb + r * DIM))[s];
        __half2 h0 = __floats2half2_rn(v.x, v.y);
        __half2 h1 = __floats2half2_rn(v.z, v.w);
        __half2 l0 = __floats2half2_rn(v.x - __low2float(h0), v.y - __high2float(h0));
        __half2 l1 = __floats2half2_rn(v.z - __low2float(h1), v.w - __high2float(h1));
        uint32_t off = r * RSTRIDE + s * 8;
        *(uint32_t*)(smem + SM_AH + off)     = *(uint32_t*)&h0;
        *(uint32_t*)(smem + SM_AH + off + 4) = *(uint32_t*)&h1;
        *(uint32_t*)(smem + SM_AL + off)     = *(uint32_t*)&l0;
        *(uint32_t*)(smem + SM_AL + off + 4) = *(uint32_t*)&l1;
    }

    // B loader lambda-ish: chunk ci into buffer b
    // (hi at SM_B + b*BUFSZ, lo at +17408)
    {
        int ci = 0, b = 0;
        const __half* eh = g_ehi + (size_t)(ci * 64) * DIM;
        const __half* el = g_elo + (size_t)(ci * 64) * DIM;
        uint32_t bb = sb + SM_B + b * BUFSZ;
        for (int u = tid; u < 1024; u += 256) {
            int n = u >> 4, s = u & 15;
            uint32_t doff = n * RSTRIDE + s * 16;
            CP_ASYNC16(bb + doff,         eh + n * DIM + s * 8);
            CP_ASYNC16(bb + 17408 + doff, el + n * DIM + s * 8);
        }
        CP_COMMIT();
    }

    const int rA = warp * 16 + g;
    float va1 = FLT_MAX, va2 = FLT_MAX, vb1 = FLT_MAX, vb2 = FLT_MAX;
    int   ia1 = 0, ib1 = 0;

    for (int i = 0; i < 64; i++) {
        if (i + 1 < 64) {
            int b = (i + 1) & 1;
            const __half* eh = g_ehi + (size_t)((i + 1) * 64) * DIM;
            const __half* el = g_elo + (size_t)((i + 1) * 64) * DIM;
            uint32_t bb = sb + SM_B + b * BUFSZ;
            for (int u = tid; u < 1024; u += 256) {
                int n = u >> 4, s = u & 15;
                uint32_t doff = n * RSTRIDE + s * 16;
                CP_ASYNC16(bb + doff,         eh + n * DIM + s * 8);
                CP_ASYNC16(bb + 17408 + doff, el + n * DIM + s * 8);
            }
            CP_COMMIT();
            CP_WAIT(1);
        } else {
            CP_WAIT(0);
        }
        __syncthreads();

        const char* Bh = smem + SM_B + (i & 1) * BUFSZ;
        const char* Bl = Bh + 17408;

        float acc[8][4];
        #pragma unroll
        for (int nt = 0; nt < 8; nt++)
            #pragma unroll
            for (int j = 0; j < 4; j++) acc[nt][j] = 0.f;

        #pragma unroll
        for (int ks = 0; ks < 8; ks++) {
            int ka = ks * 16 + t4 * 2;
            uint32_t ah0 = *(const uint32_t*)(smem + SM_AH + rA * RSTRIDE + ka * 2);
            uint32_t ah1 = *(const uint32_t*)(smem + SM_AH + (rA + 8) * RSTRIDE + ka * 2);
            uint32_t ah2 = *(const uint32_t*)(smem + SM_AH + rA * RSTRIDE + (ka + 8) * 2);
            uint32_t ah3 = *(const uint32_t*)(smem + SM_AH + (rA + 8) * RSTRIDE + (ka + 8) * 2);
            uint32_t al0 = *(const uint32_t*)(smem + SM_AL + rA * RSTRIDE + ka * 2);
            uint32_t al1 = *(const uint32_t*)(smem + SM_AL + (rA + 8) * RSTRIDE + ka * 2);
            uint32_t al2 = *(const uint32_t*)(smem + SM_AL + rA * RSTRIDE + (ka + 8) * 2);
            uint32_t al3 = *(const uint32_t*)(smem + SM_AL + (rA + 8) * RSTRIDE + (ka + 8) * 2);
            #pragma unroll
            for (int nt = 0; nt < 8; nt++) {
                int rn = nt * 8 + g;
                uint32_t bh0 = *(const uint32_t*)(Bh + rn * RSTRIDE + ka * 2);
                uint32_t bh1 = *(const uint32_t*)(Bh + rn * RSTRIDE + (ka + 8) * 2);
                uint32_t bl0 = *(const uint32_t*)(Bl + rn * RSTRIDE + ka * 2);
                uint32_t bl1 = *(const uint32_t*)(Bl + rn * RSTRIDE + (ka + 8) * 2);
                mma16816(acc[nt], ah0, ah1, ah2, ah3, bh0, bh1);
                mma16816(acc[nt], ah0, ah1, ah2, ah3, bl0, bl1);
                mma16816(acc[nt], al0, al1, al2, al3, bh0, bh1);
            }
        }

        int c0 = i * 64;
        #pragma unroll
        for (int nt = 0; nt < 8; nt++) {
            int col = c0 + nt * 8 + t4 * 2;
            float2 en2 = *(const float2*)(smem + SM_EN + col * 4);
            float d0 = fmaf(-2.f, acc[nt][0], en2.x);
            float d1 = fmaf(-2.f, acc[nt][1], en2.y);
            float d2 = fmaf(-2.f, acc[nt][2], en2.x);
            float d3 = fmaf(-2.f, acc[nt][3], en2.y);
            upd2(va1, ia1, va2, d0, col);
            upd2(va1, ia1, va2, d1, col + 1);
            upd2(vb1, ib1, vb2, d2, col);
            upd2(vb1, ib1, vb2, d3, col + 1);
        }
        __syncthreads();
    }

    // merge across the 4 lanes of each row-group (xor 1, then 2)
    #pragma unroll
    for (int m = 1; m <= 2; m <<= 1) {
        float ov1 = __shfl_xor_sync(0xffffffffu, va1, m);
        int   oi1 = __shfl_xor_sync(0xffffffffu, ia1, m);
        float ov2 = __shfl_xor_sync(0xffffffffu, va2, m);
        if (ov1 < va1 || (ov1 == va1 && oi1 < ia1)) { va2 = fminf(va1, ov2); va1 = ov1; ia1 = oi1; }
        else va2 = fminf(va2, ov1);
        ov1 = __shfl_xor_sync(0xffffffffu, vb1, m);
        oi1 = __shfl_xor_sync(0xffffffffu, ib1, m);
        ov2 = __shfl_xor_sync(0xffffffffu, vb2, m);
        if (ov1 < vb1 || (ov1 == vb1 && oi1 < ib1)) { vb2 = fminf(vb1, ov2); vb1 = ov1; ib1 = oi1; }
        else vb2 = fminf(vb2, ov1);
    }

    if (t4 == 0) {
        int rowA = row0 + warp * 16 + g;
        int rowB = rowA + 8;
        out[OFF_IND + rowA] = (float)ia1;
        out[OFF_IND + rowB] = (float)ib1;
        if (va2 - va1 < MARGIN) { int p = atomicAdd(&g_fixn, 1); if (p < 4096) g_fixlist[p] = rowA; }
        if (vb2 - vb1 < MARGIN) { int p = atomicAdd(&g_fixn, 1); if (p < 4096) g_fixlist[p] = rowB; }
    }
}

// ---------------------------------------------------------------------------
// K1b: exact fp32 rescan for ambiguous rows
// ---------------------------------------------------------------------------
__global__ void k_fix(const float* __restrict__ x, float* __restrict__ out) {
    __shared__ float xs[DIM];
    __shared__ float rv[128];
    __shared__ int   ri[128];
    int nfix = g_fixn;
    if (nfix > 4096) nfix = 4096;
    for (int j = blockIdx.x; j < nfix; j += gridDim.x) {
        int row = g_fixlist[j];
        if (threadIdx.x < 32)
            ((float4*)xs)[threadIdx.x] = ((const float4*)(x + (size_t)row * DIM))[threadIdx.x];
        __syncthreads();
        float bv = FLT_MAX; int bi = 0x7fffffff;
        for (int c = threadIdx.x; c < K_CODES; c += 128) {
            const float* e = g_embedT + (size_t)c * DIM;
            float acc = 0.f;
            #pragma unroll
            for (int d = 0; d < DIM; d++) acc = fmaf(xs[d], e[d], acc);
            float dv = fmaf(acc, -2.0f, g_enorm[c]);
            if (dv < bv) { bv = dv; bi = c; }
        }
        rv[threadIdx.x] = bv; ri[threadIdx.x] = bi;
        __syncthreads();
        if (threadIdx.x == 0) {
            float b = rv[0]; int bidx = ri[0];
            for (int t = 1; t < 128; t++) {
                float v = rv[t]; int idx = ri[t];
                if (v < b || (v == b && idx < bidx)) { b = v; bidx = idx; }
            }
            out[OFF_IND + row] = (float)bidx;
        }
        __syncthreads();
    }
}

// ---------------------------------------------------------------------------
// K2a: histogram of final indices
// ---------------------------------------------------------------------------
__global__ void k_hist(const float* __restrict__ out_c) {
    int i = blockIdx.x * 256 + threadIdx.x;
    if (i < N_ROWS) atomicAdd(&g_hist[(int)out_c[OFF_IND + i]], 1);
}

// ---------------------------------------------------------------------------
// K2b: prefix sum over hist -> offsets; cluster_size_new += 0.01*hist
// ---------------------------------------------------------------------------
__global__ void k_prefix(float* __restrict__ out) {
    __shared__ int wsum[32];
    int t = threadIdx.x;  // 1024 threads, 4 codes each
    int h0 = g_hist[t * 4], h1 = g_hist[t * 4 + 1], h2 = g_hist[t * 4 + 2], h3 = g_hist[t * 4 + 3];
    int loc = h0 + h1 + h2 + h3;
    int pre = loc;
    #pragma unroll
    for (int o = 1; o < 32; o <<= 1) {
        int n = __shfl_up_sync(0xffffffffu, pre, o);
        if ((t & 31) >= o) pre += n;
    }
    if ((t & 31) == 31) wsum[t >> 5] = pre;
    __syncthreads();
    if (t < 32) {
        int v = wsum[t];
        #pragma unroll
        for (int o = 1; o < 32; o <<= 1) {
            int n = __shfl_up_sync(0xffffffffu, v, o);
            if (t >= o) v += n;
        }
        wsum[t] = v;
    }
    __syncthreads();
    int base = pre - loc + ((t >= 32) ? wsum[(t >> 5) - 1] : 0);
    g_off[t * 4]     = base;
    g_off[t * 4 + 1] = base + h0;
    g_off[t * 4 + 2] = base + h0 + h1;
    g_off[t * 4 + 3] = base + h0 + h1 + h2;
    out[OFF_CS + t * 4]     += ONE_M_D * (float)h0;
    out[OFF_CS + t * 4 + 1] += ONE_M_D * (float)h1;
    out[OFF_CS + t * 4 + 2] += ONE_M_D * (float)h2;
    out[OFF_CS + t * 4 + 3] += ONE_M_D * (float)h3;
}

// ---------------------------------------------------------------------------
// K2c: bin rows by code
// ---------------------------------------------------------------------------
__global__ void k_scatter(const float* __restrict__ out_c) {
    int i = blockIdx.x * 256 + threadIdx.x;
    if (i >= N_ROWS) return;
    int idx = (int)out_c[OFF_IND + i];
    int pos = atomicAdd(&g_cur[idx], 1);
    g_rowlist[g_off[idx] + pos] = i;
}

// ---------------------------------------------------------------------------
// K2d: per-code gather-sum into embed_avg_new (one warp per code, no atomics)
// ---------------------------------------------------------------------------
__global__ void __launch_bounds__(256)
k_avg(const float* __restrict__ x, float* __restrict__ out) {
    int c    = blockIdx.x * 8 + (threadIdx.x >> 5);
    int lane = threadIdx.x & 31;
    int cnt  = g_hist[c];
    int base = g_off[c];
    float4 s = make_float4(0.f, 0.f, 0.f, 0.f);
    for (int j = 0; j < cnt; j++) {
        int r = g_rowlist[base + j];
        float4 v = ((const float4*)(x + (size_t)r * DIM))[lane];
        s.x += v.x; s.y += v.y; s.z += v.z; s.w += v.w;
    }
    if (cnt > 0) {
        out[OFF_EAVG + (size_t)(lane * 4 + 0) * K_CODES + c] += ONE_M_D * s.x;
        out[OFF_EAVG + (size_t)(lane * 4 + 1) * K_CODES + c] += ONE_M_D * s.y;
        out[OFF_EAVG + (size_t)(lane * 4 + 2) * K_CODES + c] += ONE_M_D * s.z;
        out[OFF_EAVG + (size_t)(lane * 4 + 3) * K_CODES + c] += ONE_M_D * s.w;
    }
}

// ---------------------------------------------------------------------------
// K3: quantize gather + loss
// ---------------------------------------------------------------------------
__global__ void __launch_bounds__(256)
k_post(const float* __restrict__ x, float* __restrict__ out) {
    int row  = blockIdx.x * 8 + (threadIdx.x >> 5);
    int lane = threadIdx.x & 31;
    int idx  = (int)out[OFF_IND + row];
    float4 q  = ((const float4*)(g_embedT + (size_t)idx * DIM))[lane];
    float4 xv = ((const float4*)(x + (size_t)row * DIM))[lane];
    ((float4*)(out + OFF_Q + (size_t)row * DIM))[lane] = q;
    float d0 = q.x - xv.x, d1 = q.y - xv.y, d2 = q.z - xv.z, d3 = q.w - xv.w;
    float lsum = d0 * d0 + d1 * d1 + d2 * d2 + d3 * d3;
    #pragma unroll
    for (int o = 16; o > 0; o >>= 1) lsum += __shfl_down_sync(0xffffffffu, lsum, o);
    if (lane == 0) atomicAdd(&g_loss, (double)lsum);
}

// ---------------------------------------------------------------------------
// K4: n = sum(cluster_size_new), n_small count
// ---------------------------------------------------------------------------
__global__ void k_scalar(float* __restrict__ out) {
    __shared__ float ssum[32];
    __shared__ int   scnt[32];
    int t = threadIdx.x;
    float s = 0.f; int c = 0;
    #pragma unroll
    for (int j = 0; j < 4; j++) {
        float v = out[OFF_CS + t + j * 1024];
        s += v;
        c += (v < 1.0f) ? 1 : 0;
    }
    #pragma unroll
    for (int o = 16; o > 0; o >>= 1) {
        s += __shfl_down_sync(0xffffffffu, s, o);
        c += __shfl_down_sync(0xffffffffu, c, o);
    }
    if ((t & 31) == 0) { ssum[t >> 5] = s; scnt[t >> 5] = c; }
    __syncthreads();
    if (t < 32) {
        s = ssum[t]; c = scnt[t];
        #pragma unroll
        for (int o = 16; o > 0; o >>= 1) {
            s += __shfl_down_sync(0xffffffffu, s, o);
            c += __shfl_down_sync(0xffffffffu, c, o);
        }
        if (t == 0) { g_n = s; out[OFF_NSMALL] = (float)c; }
    }
}

// ---------------------------------------------------------------------------
// K5: embed_new = embed_avg_new / cs_norm; finalize loss
// ---------------------------------------------------------------------------
__global__ void k_final(float* __restrict__ out) {
    int i = blockIdx.x * 256 + threadIdx.x;
    if (i < DIM * K_CODES) {
        int k = i & (K_CODES - 1);
        float n   = g_n;
        float cs  = out[OFF_CS + k];
        float csn = (cs + EPS) / (n + (float)K_CODES * EPS) * n;
        out[OFF_ENEW + i] = out[OFF_EAVG + i] / csn;
    }
    if (i == 0) out[OFF_LOSS] = (float)(g_loss / ((double)N_ROWS * (double)DIM));
}

// ---------------------------------------------------------------------------
extern "C" void kernel_launch(void* const* d_in, const int* in_sizes, int n_in,
                              void* d_out, int out_size) {
    const float* x            = (const float*)d_in[0];
    const float* embed        = (const float*)d_in[1];
    const float* cluster_size = (const float*)d_in[2];
    const float* embed_avg    = (const float*)d_in[3];
    float* out = (float*)d_out;

    cudaFuncSetAttribute(k_mma, cudaFuncAttributeMaxDynamicSharedMemorySize, SMEM_MMA_BYTES);

    k_init<<<(DIM * K_CODES + 255) / 256, 256>>>(cluster_size, embed_avg, out);
    k_prepe<<<(DIM * K_CODES + 255) / 256, 256>>>(embed);
    k_enorm<<<(K_CODES * 32) / 256, 256>>>();
    k_mma<<<N_ROWS / 128, 256, SMEM_MMA_BYTES>>>(x, out);
    k_fix<<<128, 128>>>(x, out);
    k_hist<<<N_ROWS / 256, 256>>>(out);
    k_prefix<<<1, 1024>>>(out);
    k_scatter<<<N_ROWS / 256, 256>>>(out);
    k_avg<<<K_CODES / 8, 256>>>(x, out);
    k_post<<<N_ROWS / 8, 256>>>(x, out);
    k_scalar<<<1, 1024>>>(out);
    k_final<<<(DIM * K_CODES + 255) / 256, 256>>>(out);
}